// round 1
// baseline (speedup 1.0000x reference)
#include <cuda_runtime.h>
#include <math.h>

// Problem constants
#define DIMM   768
#define NHEADS 12
#define HDIM   64
#define MLPD   3072
#define NDEPTH 12
#define BATCH  16
#define SEQ    512
#define MROWS  (BATCH*SEQ)   // 8192
#define NZ     (BATCH*NHEADS) // 192

// ---------------- scratch (static device, no allocation) ----------------
__device__ float g_x [(size_t)MROWS*DIMM];
__device__ float g_x2[(size_t)MROWS*DIMM];
__device__ float g_ln[(size_t)MROWS*DIMM];
__device__ float g_q [(size_t)MROWS*DIMM];
__device__ float g_kt[(size_t)NZ*HDIM*SEQ];     // per-head K^T: [z][d][n]
__device__ float g_v [(size_t)MROWS*DIMM];
__device__ float g_s [(size_t)NZ*SEQ*SEQ];      // scores/probs
__device__ float g_h [(size_t)MROWS*MLPD];      // mlp hidden (also temp for K)

// ---------------- helpers ----------------
__device__ __forceinline__ float tf32r(float x){
    unsigned r; asm("cvt.rna.tf32.f32 %0, %1;" : "=r"(r) : "f"(x));
    return __uint_as_float(r);
}

__device__ __forceinline__ void mma_tf32(float* d, const float* a, const float* b){
    asm volatile(
        "mma.sync.aligned.m16n8k8.row.col.f32.tf32.tf32.f32 "
        "{%0,%1,%2,%3}, {%4,%5,%6,%7}, {%8,%9}, {%0,%1,%2,%3};\n"
        : "+f"(d[0]), "+f"(d[1]), "+f"(d[2]), "+f"(d[3])
        : "r"(__float_as_uint(a[0])), "r"(__float_as_uint(a[1])),
          "r"(__float_as_uint(a[2])), "r"(__float_as_uint(a[3])),
          "r"(__float_as_uint(b[0])), "r"(__float_as_uint(b[1])));
}

__device__ __forceinline__ float gelu_exact(float v){
    return 0.5f * v * (1.0f + erff(v * 0.70710678118654752440f));
}

// ---------------- GEMM: C = A(MxK,row) * B(KxN,row), fp32 in/out, tf32 mma ----
// EPI bits: 1 = +bias[col], 2 = gelu, 4 = +residual, 8 = *scale
struct GP {
    const float* A; const float* B; float* C;
    const float* bias; const float* R;
    int lda, ldb, ldc, ldr;
    long sAb, sAh, sBb, sBh, sCb, sCh, sRb, sRh;
    int H;            // heads per batch for z decomposition (z = b*H + h)
    float scale;
    int Ktiles;       // K / 16
};

template<int BM, int BN, int EPI>
__launch_bounds__(256, 2)
__global__ void gemm_tf32(GP p){
    constexpr int BK   = 16;
    constexpr int ASTR = BK + 4;     // 20: fragment reads hit 4r+c -> 32 distinct banks
    constexpr int BSTR = BN + 8;     // fragment reads hit 8k+n -> 32 distinct banks
    constexpr int AF4  = BM*BK/1024; // float4 per thread for A tile
    constexpr int BF4  = BK*BN/1024;
    constexpr int WTM  = BM/4, WTN = BN/2;
    constexpr int MT   = WTM/16, NT = WTN/8;

    __shared__ float As[2][BM*ASTR];
    __shared__ float Bs[2][BK*BSTR];

    const int tid  = threadIdx.x;
    const int lane = tid & 31;
    const int warp = tid >> 5;
    const int wm   = warp >> 1;       // 0..3
    const int wn   = warp & 1;        // 0..1

    const int z  = blockIdx.z;
    const int zb = z / p.H, zh = z % p.H;

    const float* Ag = p.A + (long)zb*p.sAb + (long)zh*p.sAh + (long)blockIdx.y*BM*p.lda;
    const float* Bg = p.B + (long)zb*p.sBb + (long)zh*p.sBh + (long)blockIdx.x*BN;

    float acc[MT][NT][4];
    #pragma unroll
    for(int i=0;i<MT;i++)
        #pragma unroll
        for(int j=0;j<NT;j++){
            acc[i][j][0]=0.f; acc[i][j][1]=0.f; acc[i][j][2]=0.f; acc[i][j][3]=0.f;
        }

    float4 ra[AF4], rb[BF4];

    auto ldAg = [&](int kt){
        #pragma unroll
        for(int i=0;i<AF4;i++){
            int idx = tid + i*256;
            int row = idx >> 2, c4 = idx & 3;
            ra[i] = *(const float4*)(Ag + (long)row*p.lda + kt*BK + c4*4);
        }
    };
    auto ldBg = [&](int kt){
        #pragma unroll
        for(int i=0;i<BF4;i++){
            int idx = tid + i*256;
            int k  = idx / (BN/4), c4 = idx % (BN/4);
            rb[i] = *(const float4*)(Bg + (long)(kt*BK + k)*p.ldb + c4*4);
        }
    };
    auto stAs = [&](int buf){
        #pragma unroll
        for(int i=0;i<AF4;i++){
            int idx = tid + i*256;
            int row = idx >> 2, c4 = idx & 3;
            float4 v = ra[i];
            v.x=tf32r(v.x); v.y=tf32r(v.y); v.z=tf32r(v.z); v.w=tf32r(v.w);
            *(float4*)&As[buf][row*ASTR + c4*4] = v;
        }
    };
    auto stBs = [&](int buf){
        #pragma unroll
        for(int i=0;i<BF4;i++){
            int idx = tid + i*256;
            int k  = idx / (BN/4), c4 = idx % (BN/4);
            float4 v = rb[i];
            v.x=tf32r(v.x); v.y=tf32r(v.y); v.z=tf32r(v.z); v.w=tf32r(v.w);
            *(float4*)&Bs[buf][k*BSTR + c4*4] = v;
        }
    };

    ldAg(0); ldBg(0);
    stAs(0); stBs(0);
    __syncthreads();

    const int nk = p.Ktiles;
    for(int kt = 0; kt < nk; kt++){
        const int buf = kt & 1;
        if(kt + 1 < nk){ ldAg(kt+1); ldBg(kt+1); }

        #pragma unroll
        for(int ks=0; ks<2; ks++){
            float a[MT][4]; float b[NT][2];
            const int cA = ks*8 + (lane & 3);
            #pragma unroll
            for(int mt=0; mt<MT; mt++){
                const int r0 = wm*WTM + mt*16 + (lane >> 2);
                a[mt][0] = As[buf][ r0     *ASTR + cA    ];
                a[mt][1] = As[buf][(r0+8)  *ASTR + cA    ];
                a[mt][2] = As[buf][ r0     *ASTR + cA + 4];
                a[mt][3] = As[buf][(r0+8)  *ASTR + cA + 4];
            }
            const int kB = ks*8 + (lane & 3);
            #pragma unroll
            for(int nt=0; nt<NT; nt++){
                const int n = wn*WTN + nt*8 + (lane >> 2);
                b[nt][0] = Bs[buf][ kB    *BSTR + n];
                b[nt][1] = Bs[buf][(kB+4) *BSTR + n];
            }
            #pragma unroll
            for(int mt=0; mt<MT; mt++)
                #pragma unroll
                for(int nt=0; nt<NT; nt++)
                    mma_tf32(acc[mt][nt], a[mt], b[nt]);
        }

        if(kt + 1 < nk){ stAs(buf ^ 1); stBs(buf ^ 1); }
        __syncthreads();
    }

    // epilogue
    float* Cg = p.C + (long)zb*p.sCb + (long)zh*p.sCh
                    + (long)blockIdx.y*BM*p.ldc + (long)blockIdx.x*BN;
    const float* Rg = nullptr;
    if(EPI & 4)
        Rg = p.R + (long)zb*p.sRb + (long)zh*p.sRh
                 + (long)blockIdx.y*BM*p.ldr + (long)blockIdx.x*BN;

    #pragma unroll
    for(int mt=0; mt<MT; mt++){
        #pragma unroll
        for(int nt=0; nt<NT; nt++){
            const int col = wn*WTN + nt*8 + 2*(lane & 3);
            #pragma unroll
            for(int hh=0; hh<2; hh++){
                const int row = wm*WTM + mt*16 + (lane >> 2) + hh*8;
                float v0 = acc[mt][nt][hh*2], v1 = acc[mt][nt][hh*2+1];
                if(EPI & 8){ v0 *= p.scale; v1 *= p.scale; }
                if(EPI & 1){
                    const int gc = blockIdx.x*BN + col;
                    v0 += p.bias[gc]; v1 += p.bias[gc+1];
                }
                if(EPI & 2){ v0 = gelu_exact(v0); v1 = gelu_exact(v1); }
                if(EPI & 4){
                    float2 rv = *(const float2*)(Rg + (long)row*p.ldr + col);
                    v0 += rv.x; v1 += rv.y;
                }
                *(float2*)(Cg + (long)row*p.ldc + col) = make_float2(v0, v1);
            }
        }
    }
}

// ---------------- LayerNorm (row = 768) ----------------
__global__ void ln_kernel(const float* __restrict__ x, const float* __restrict__ w,
                          const float* __restrict__ b, float* __restrict__ out){
    const int row = blockIdx.x;
    const int tid = threadIdx.x; // 256
    const float* xr = x + (size_t)row*DIMM;
    float a0 = xr[tid], a1 = xr[tid+256], a2 = xr[tid+512];

    float s  = a0 + a1 + a2;
    float s2 = a0*a0 + a1*a1 + a2*a2;
    // block reduce (sum, sumsq)
    __shared__ float shs[8], shq[8];
    const int lane = tid & 31, wrp = tid >> 5;
    #pragma unroll
    for(int o=16;o;o>>=1){ s += __shfl_xor_sync(~0u,s,o); s2 += __shfl_xor_sync(~0u,s2,o); }
    if(lane==0){ shs[wrp]=s; shq[wrp]=s2; }
    __syncthreads();
    if(wrp==0){
        s  = (lane<8)? shs[lane] : 0.f;
        s2 = (lane<8)? shq[lane] : 0.f;
        #pragma unroll
        for(int o=4;o;o>>=1){ s += __shfl_xor_sync(~0u,s,o); s2 += __shfl_xor_sync(~0u,s2,o); }
        if(lane==0){ shs[0]=s; shq[0]=s2; }
    }
    __syncthreads();
    const float mu  = shs[0] * (1.f/DIMM);
    const float var = shq[0] * (1.f/DIMM) - mu*mu;
    const float inv = rsqrtf(var + 1e-5f);

    float* orow = out + (size_t)row*DIMM;
    orow[tid    ] = (a0 - mu)*inv*w[tid    ] + b[tid    ];
    orow[tid+256] = (a1 - mu)*inv*w[tid+256] + b[tid+256];
    orow[tid+512] = (a2 - mu)*inv*w[tid+512] + b[tid+512];
}

// ---------------- K reformat: [8192,768] -> per-head [z][d][n] ----------------
__global__ void kreform(const float* __restrict__ kin, float* __restrict__ kt){
    __shared__ float t[32][33];
    const int z = blockIdx.z, bb = z / NHEADS, hh = z % NHEADS;
    const int n0 = blockIdx.x*32, d0 = blockIdx.y*32;
    const int tx = threadIdx.x & 31, ty = threadIdx.x >> 5;  // 32 x 8
    #pragma unroll
    for(int k=0;k<4;k++){
        const int n = n0 + ty + 8*k;
        t[ty + 8*k][tx] = kin[(size_t)(bb*SEQ + n)*DIMM + hh*HDIM + d0 + tx];
    }
    __syncthreads();
    #pragma unroll
    for(int k=0;k<4;k++){
        const int d = d0 + ty + 8*k;
        kt[((size_t)z*HDIM + d)*SEQ + n0 + tx] = t[tx][ty + 8*k];
    }
}

// ---------------- softmax over rows of 512 (warp per row) ----------------
__global__ void softmax_kernel(float* __restrict__ s){
    const int row  = blockIdx.x*8 + (threadIdx.x >> 5);
    const int lane = threadIdx.x & 31;
    float* r = s + (size_t)row*SEQ;
    float v[16];
    float m = -1e30f;
    #pragma unroll
    for(int i=0;i<16;i++){ v[i] = r[lane + i*32]; m = fmaxf(m, v[i]); }
    #pragma unroll
    for(int o=16;o;o>>=1) m = fmaxf(m, __shfl_xor_sync(~0u,m,o));
    float sum = 0.f;
    #pragma unroll
    for(int i=0;i<16;i++){ v[i] = __expf(v[i]-m); sum += v[i]; }
    #pragma unroll
    for(int o=16;o;o>>=1) sum += __shfl_xor_sync(~0u,sum,o);
    const float inv = 1.f/sum;
    #pragma unroll
    for(int i=0;i<16;i++) r[lane + i*32] = v[i]*inv;
}

// ---------------- host ----------------
static GP mkgp(const float* A, const float* B, float* C, const float* bias,
               const float* R, int lda, int ldb, int ldc, int ldr, int Ktiles){
    GP p{};
    p.A=A; p.B=B; p.C=C; p.bias=bias; p.R=R;
    p.lda=lda; p.ldb=ldb; p.ldc=ldc; p.ldr=ldr;
    p.sAb=p.sAh=p.sBb=p.sBh=p.sCb=p.sCh=p.sRb=p.sRh=0;
    p.H=1; p.scale=1.f; p.Ktiles=Ktiles;
    return p;
}

extern "C" void kernel_launch(void* const* d_in, const int* in_sizes, int n_in,
                              void* d_out, int out_size){
    const float* x    = (const float*)d_in[0];
    const float* ln_w = (const float*)d_in[1];
    const float* ln_b = (const float*)d_in[2];
    const float* wq   = (const float*)d_in[3];
    const float* bq   = (const float*)d_in[4];
    const float* wk   = (const float*)d_in[5];
    const float* bk   = (const float*)d_in[6];
    const float* wv   = (const float*)d_in[7];
    const float* bv   = (const float*)d_in[8];
    const float* w1   = (const float*)d_in[9];
    const float* b1   = (const float*)d_in[10];
    const float* w2   = (const float*)d_in[11];
    const float* b2   = (const float*)d_in[12];

    float *px, *px2, *pln, *pq, *pkt, *pv, *ps, *ph;
    cudaGetSymbolAddress((void**)&px , g_x );
    cudaGetSymbolAddress((void**)&px2, g_x2);
    cudaGetSymbolAddress((void**)&pln, g_ln);
    cudaGetSymbolAddress((void**)&pq , g_q );
    cudaGetSymbolAddress((void**)&pkt, g_kt);
    cudaGetSymbolAddress((void**)&pv , g_v );
    cudaGetSymbolAddress((void**)&ps , g_s );
    cudaGetSymbolAddress((void**)&ph , g_h );

    cudaMemcpyAsync(px, x, (size_t)MROWS*DIMM*sizeof(float), cudaMemcpyDeviceToDevice);

    for(int l=0; l<NDEPTH; l++){
        // --- attention block ---
        ln_kernel<<<MROWS,256>>>(px, ln_w, ln_b, pln);

        { GP p = mkgp(pln, wq, pq, bq, nullptr, DIMM, DIMM, DIMM, 0, DIMM/16);
          gemm_tf32<128,128,1><<<dim3(DIMM/128, MROWS/128, 1), 256>>>(p); }
        { GP p = mkgp(pln, wk, ph, bk, nullptr, DIMM, DIMM, DIMM, 0, DIMM/16);
          gemm_tf32<128,128,1><<<dim3(DIMM/128, MROWS/128, 1), 256>>>(p); }
        { GP p = mkgp(pln, wv, pv, bv, nullptr, DIMM, DIMM, DIMM, 0, DIMM/16);
          gemm_tf32<128,128,1><<<dim3(DIMM/128, MROWS/128, 1), 256>>>(p); }

        kreform<<<dim3(SEQ/32, HDIM/32, NZ), 256>>>(ph, pkt);

        // scores: S = (Q Kt) * 1/8 ; per head z
        { GP p = mkgp(pq, pkt, ps, nullptr, nullptr, DIMM, SEQ, SEQ, 0, HDIM/16);
          p.H = NHEADS; p.scale = 0.125f;
          p.sAb = (long)SEQ*DIMM;      p.sAh = HDIM;
          p.sBb = (long)NHEADS*HDIM*SEQ; p.sBh = (long)HDIM*SEQ;
          p.sCb = (long)NHEADS*SEQ*SEQ;  p.sCh = (long)SEQ*SEQ;
          gemm_tf32<128,128,8><<<dim3(SEQ/128, SEQ/128, NZ), 256>>>(p); }

        softmax_kernel<<<NZ*SEQ/8, 256>>>(ps);

        // AV: x2 = P V + x (residual fused)
        { GP p = mkgp(ps, pv, px2, nullptr, px, SEQ, DIMM, DIMM, DIMM, SEQ/16);
          p.H = NHEADS;
          p.sAb = (long)NHEADS*SEQ*SEQ; p.sAh = (long)SEQ*SEQ;
          p.sBb = (long)SEQ*DIMM;       p.sBh = HDIM;
          p.sCb = (long)SEQ*DIMM;       p.sCh = HDIM;
          p.sRb = (long)SEQ*DIMM;       p.sRh = HDIM;
          gemm_tf32<128,64,4><<<dim3(HDIM/64, SEQ/128, NZ), 256>>>(p); }

        // --- MLP block ---
        ln_kernel<<<MROWS,256>>>(px2, ln_w, ln_b, pln);

        { GP p = mkgp(pln, w1, ph, b1, nullptr, DIMM, MLPD, MLPD, 0, DIMM/16);
          gemm_tf32<128,128,3><<<dim3(MLPD/128, MROWS/128, 1), 256>>>(p); }  // bias+gelu

        { GP p = mkgp(ph, w2, px, b2, px2, MLPD, DIMM, DIMM, DIMM, MLPD/16);
          gemm_tf32<128,128,5><<<dim3(DIMM/128, MROWS/128, 1), 256>>>(p); }  // bias+resid
    }

    cudaMemcpyAsync(d_out, px, (size_t)MROWS*DIMM*sizeof(float), cudaMemcpyDeviceToDevice);
}

// round 3
// speedup vs baseline: 1.0385x; 1.0385x over previous
#include <cuda_runtime.h>
#include <math.h>
#include <stdint.h>

// Problem constants
#define DIMM   768
#define NHEADS 12
#define HDIM   64
#define MLPD   3072
#define NDEPTH 12
#define BATCH  16
#define SEQ    512
#define MROWS  (BATCH*SEQ)    // 8192
#define NZ     (BATCH*NHEADS) // 192
#define QKVN   (3*DIMM)       // 2304

// ---------------- scratch (static device, no allocation) ----------------
__device__ float g_x   [(size_t)MROWS*DIMM];
__device__ float g_x2  [(size_t)MROWS*DIMM];
__device__ float g_ln  [(size_t)MROWS*DIMM];
__device__ float g_qkv [(size_t)MROWS*QKVN];     // fused QKV output
__device__ float g_vt  [(size_t)NZ*HDIM*SEQ];    // per-head V^T: [z][d][n]
__device__ float g_s   [(size_t)NZ*SEQ*SEQ];     // scores/probs
__device__ float g_h   [(size_t)MROWS*MLPD];     // mlp hidden
__device__ float g_wqkvT[(size_t)QKVN*DIMM];     // [2304,768] tf32-rounded, [N,K]
__device__ float g_w1T [(size_t)MLPD*DIMM];      // [3072,768]
__device__ float g_w2T [(size_t)DIMM*MLPD];      // [768,3072]
__device__ float g_bqkv[QKVN];

// ---------------- helpers ----------------
__device__ __forceinline__ float tf32r(float x){
    unsigned r; asm("cvt.rna.tf32.f32 %0, %1;" : "=r"(r) : "f"(x));
    return __uint_as_float(r);
}
__device__ __forceinline__ float gelu_exact(float v){
    return 0.5f * v * (1.0f + erff(v * 0.70710678118654752440f));
}
__device__ __forceinline__ void mma_tf32(float* d, const float* a, const float* b){
    asm volatile(
        "mma.sync.aligned.m16n8k8.row.col.f32.tf32.tf32.f32 "
        "{%0,%1,%2,%3}, {%4,%5,%6,%7}, {%8,%9}, {%0,%1,%2,%3};\n"
        : "+f"(d[0]), "+f"(d[1]), "+f"(d[2]), "+f"(d[3])
        : "r"(__float_as_uint(a[0])), "r"(__float_as_uint(a[1])),
          "r"(__float_as_uint(a[2])), "r"(__float_as_uint(a[3])),
          "r"(__float_as_uint(b[0])), "r"(__float_as_uint(b[1])));
}

// =========================================================================
// Fragment-layout tf32 GEMM.
//   C[M,N] = A[M,K] (row-major, K contiguous) * B[N,K]^T (row-major, K contig)
//   BM=128, BN in {128,64}, BK=32. 8 warps as 2(m) x 4(n). MT=4, NT=BN/32.
//
// Shared layouts (per stage, per K-slice of 8):
//   A 16B unit V(row,k) = (k>>3)<<8 | (row>>4)<<5 | (row&7)<<2 | (k&3)
//      swizzled sa = V ^ (((V>>3)^(V>>8))&3); unit holds
//      [+0]=(r,c) [+4]=(r+8,c) [+8]=(r,c+4) [+12]=(r+8,c+4)  == a-fragment
//   B 8B unit  U(n,k) = (k>>3)<<S2 | (k&3)<<S1 | n   (S1=log2 BN, S2=S1+2)
//      swizzled sb = U ^ ((((U>>S1)^(U>>S2))&3)<<2); unit holds
//      [+0]=(k,n) [+4]=(k+4,n)  == b-fragment
// Fragment loads: 1 LDS.128 (A) / 1 LDS.64 (B), bank-conflict-free.
//
// EPI bits: 1=+bias[col], 2=gelu, 4=+residual, 8=*scale, 16=round to tf32
// =========================================================================
struct P2 {
    const float* A; const float* B; float* C;
    const float* bias; const float* R;
    int lda, ldb, ldc, ldr;
    long sAb, sAh, sBb, sBh, sCb, sCh, sRb, sRh;
    int H;          // z = zb*H + zh decomposition
    float scale;
    int nk;         // K / 32
};

template<int BN, int EPI>
__global__ __launch_bounds__(256, 2) void gemm2(P2 p){
    constexpr int BM = 128, BK = 32;
    constexpr int S1 = (BN == 128) ? 7 : 6;
    constexpr int S2 = S1 + 2;
    constexpr int WTN = BN/4, NT = WTN/8, MT = 4;
    constexpr int ABYTES = BM*BK*4;               // 16384
    constexpr int BBYTES = BN*BK*4;
    constexpr int BNF = BN*BK/1024;               // float4 loads per thread for B

    extern __shared__ char sm[];
    const int tid  = threadIdx.x;
    const int lane = tid & 31;
    const int warp = tid >> 5;
    const int wm   = warp >> 2;          // 0..1
    const int wn   = warp & 3;           // 0..3

    const int z  = blockIdx.z;
    const int zb = z / p.H, zh = z % p.H;

    const float* Ag = p.A + (long)zb*p.sAb + (long)zh*p.sAh + (long)blockIdx.y*BM*p.lda;
    const float* Bg = p.B + (long)zb*p.sBb + (long)zh*p.sBh + (long)blockIdx.x*BN*p.ldb;

    float acc[MT][NT][4];
    #pragma unroll
    for(int i=0;i<MT;i++)
        #pragma unroll
        for(int j=0;j<NT;j++){
            acc[i][j][0]=0.f; acc[i][j][1]=0.f; acc[i][j][2]=0.f; acc[i][j][3]=0.f;
        }

    float4 ra[4], rb[BNF];

    auto ldgA = [&](int kt){
        #pragma unroll
        for(int t=0;t<4;t++){
            int i = tid + t*256, row = i>>3, kq = i&7;
            ra[t] = *(const float4*)(Ag + (long)row*p.lda + kt*BK + kq*4);
        }
    };
    auto stsA = [&](int s){
        char* ab = sm + s*(ABYTES+BBYTES);
        #pragma unroll
        for(int t=0;t<4;t++){
            int i = tid + t*256, row = i>>3, kq = i&7;
            const float* e = (const float*)&ra[t];
            #pragma unroll
            for(int j=0;j<4;j++){
                uint32_t V  = ((uint32_t)(kq>>1)<<8) | ((uint32_t)(row>>4)<<5)
                            | ((uint32_t)(row&7)<<2) | (uint32_t)j;
                uint32_t sa = V ^ (((V>>3)^(V>>8))&3);
                *(float*)(ab + sa*16 + ((row>>3)&1)*4 + (kq&1)*8) = e[j];
            }
        }
    };
    auto ldgB = [&](int kt){
        #pragma unroll
        for(int t=0;t<BNF;t++){
            int i = tid + t*256, n = i>>3, kq = i&7;
            rb[t] = *(const float4*)(Bg + (long)n*p.ldb + kt*BK + kq*4);
        }
    };
    auto stsB = [&](int s){
        char* bb = sm + s*(ABYTES+BBYTES) + ABYTES;
        #pragma unroll
        for(int t=0;t<BNF;t++){
            int i = tid + t*256, n = i>>3, kq = i&7;
            const float* e = (const float*)&rb[t];
            #pragma unroll
            for(int j=0;j<4;j++){
                uint32_t U  = ((uint32_t)(kq>>1)<<S2) | ((uint32_t)j<<S1) | (uint32_t)n;
                uint32_t f  = ((U>>S1)^(U>>S2))&3;
                uint32_t sb = U ^ (f<<2);
                *(float*)(bb + sb*8 + (kq&1)*4) = e[j];
            }
        }
    };

    auto mmaks = [&](int s, int ks){
        const char* ab = sm + s*(ABYTES+BBYTES);
        const char* bb = ab + ABYTES;
        float af[MT][4]; float bf[NT][2];
        const uint32_t fA = (((uint32_t)lane>>3) ^ (uint32_t)ks) & 3;
        #pragma unroll
        for(int mt=0; mt<MT; mt++){
            uint32_t V  = ((uint32_t)ks<<8) | ((uint32_t)(wm*4+mt)<<5) | (uint32_t)lane;
            uint32_t sa = V ^ fA;
            float4 v = *(const float4*)(ab + sa*16);
            af[mt][0]=v.x; af[mt][1]=v.y; af[mt][2]=v.z; af[mt][3]=v.w;
        }
        const uint32_t fB = (((uint32_t)lane&3) ^ (uint32_t)ks) & 3;
        #pragma unroll
        for(int nt=0; nt<NT; nt++){
            uint32_t n  = (uint32_t)(wn*WTN + nt*8 + (lane>>2));
            uint32_t U  = ((uint32_t)ks<<S2) | ((uint32_t)(lane&3)<<S1) | n;
            uint32_t sb = U ^ (fB<<2);
            float2 v = *(const float2*)(bb + sb*8);
            bf[nt][0]=v.x; bf[nt][1]=v.y;
        }
        #pragma unroll
        for(int mt=0; mt<MT; mt++)
            #pragma unroll
            for(int nt=0; nt<NT; nt++)
                mma_tf32(acc[mt][nt], af[mt], bf[nt]);
    };

    // prologue
    ldgA(0); ldgB(0); stsA(0); stsB(0);
    __syncthreads();

    const int nk = p.nk;
    for(int kt = 0; kt < nk; kt++){
        const int buf = kt & 1, nb = buf ^ 1;
        const bool pf = (kt + 1 < nk);
        if(pf) ldgA(kt+1);
        mmaks(buf, 0); mmaks(buf, 1);
        if(pf){ stsA(nb); ldgB(kt+1); }
        mmaks(buf, 2); mmaks(buf, 3);
        if(pf) stsB(nb);
        __syncthreads();
    }

    // ---------------- epilogue ----------------
    float* Cg = p.C + (long)zb*p.sCb + (long)zh*p.sCh
                    + (long)blockIdx.y*BM*p.ldc + (long)blockIdx.x*BN;
    const float* Rg = nullptr;
    if(EPI & 4)
        Rg = p.R + (long)zb*p.sRb + (long)zh*p.sRh
                 + (long)blockIdx.y*BM*p.ldr + (long)blockIdx.x*BN;

    #pragma unroll
    for(int mt=0; mt<MT; mt++){
        #pragma unroll
        for(int nt=0; nt<NT; nt++){
            const int col = wn*WTN + nt*8 + 2*(lane&3);
            #pragma unroll
            for(int hh=0; hh<2; hh++){
                const int row = wm*64 + mt*16 + (lane>>2) + hh*8;
                float v0 = acc[mt][nt][hh*2], v1 = acc[mt][nt][hh*2+1];
                if(EPI & 8){ v0 *= p.scale; v1 *= p.scale; }
                if(EPI & 1){
                    const int gc = blockIdx.x*BN + col;
                    v0 += p.bias[gc]; v1 += p.bias[gc+1];
                }
                if(EPI & 2){ v0 = gelu_exact(v0); v1 = gelu_exact(v1); }
                if(EPI & 16){ v0 = tf32r(v0); v1 = tf32r(v1); }
                if(EPI & 4){
                    float2 rv = *(const float2*)(Rg + (long)row*p.ldr + col);
                    v0 += rv.x; v1 += rv.y;
                }
                *(float2*)(Cg + (long)row*p.ldc + col) = make_float2(v0, v1);
            }
        }
    }
}

// ---------------- LayerNorm (row = 768), output rounded to tf32 ----------------
__global__ void ln_kernel(const float* __restrict__ x, const float* __restrict__ w,
                          const float* __restrict__ b, float* __restrict__ out){
    const int row = blockIdx.x;
    const int tid = threadIdx.x;
    const float* xr = x + (size_t)row*DIMM;
    float a0 = xr[tid], a1 = xr[tid+256], a2 = xr[tid+512];

    float s  = a0 + a1 + a2;
    float s2 = a0*a0 + a1*a1 + a2*a2;
    __shared__ float shs[8], shq[8];
    const int lane = tid & 31, wrp = tid >> 5;
    #pragma unroll
    for(int o=16;o;o>>=1){ s += __shfl_xor_sync(~0u,s,o); s2 += __shfl_xor_sync(~0u,s2,o); }
    if(lane==0){ shs[wrp]=s; shq[wrp]=s2; }
    __syncthreads();
    if(wrp==0){
        s  = (lane<8)? shs[lane] : 0.f;
        s2 = (lane<8)? shq[lane] : 0.f;
        #pragma unroll
        for(int o=4;o;o>>=1){ s += __shfl_xor_sync(~0u,s,o); s2 += __shfl_xor_sync(~0u,s2,o); }
        if(lane==0){ shs[0]=s; shq[0]=s2; }
    }
    __syncthreads();
    const float mu  = shs[0] * (1.f/DIMM);
    const float var = shq[0] * (1.f/DIMM) - mu*mu;
    const float inv = rsqrtf(var + 1e-5f);

    float* orow = out + (size_t)row*DIMM;
    orow[tid    ] = tf32r((a0 - mu)*inv*w[tid    ] + b[tid    ]);
    orow[tid+256] = tf32r((a1 - mu)*inv*w[tid+256] + b[tid+256]);
    orow[tid+512] = tf32r((a2 - mu)*inv*w[tid+512] + b[tid+512]);
}

// ---------------- V reformat: qkv V-cols -> per-head [z][d][n] ----------------
__global__ void vreform(const float* __restrict__ qkv, float* __restrict__ vt){
    __shared__ float t[32][33];
    const int z = blockIdx.z, bb = z / NHEADS, hh = z % NHEADS;
    const int n0 = blockIdx.x*32, d0 = blockIdx.y*32;
    const int tx = threadIdx.x & 31, ty = threadIdx.x >> 5;
    #pragma unroll
    for(int k=0;k<4;k++){
        const int n = n0 + ty + 8*k;
        t[ty + 8*k][tx] = qkv[(size_t)(bb*SEQ + n)*QKVN + 2*DIMM + hh*HDIM + d0 + tx];
    }
    __syncthreads();
    #pragma unroll
    for(int k=0;k<4;k++){
        const int d = d0 + ty + 8*k;
        vt[((size_t)z*HDIM + d)*SEQ + n0 + tx] = t[tx][ty + 8*k];
    }
}

// ---------------- softmax over rows of 512 (warp per row), rounds P to tf32 ----
__global__ void softmax_kernel(float* __restrict__ s){
    const int row  = blockIdx.x*8 + (threadIdx.x >> 5);
    const int lane = threadIdx.x & 31;
    float* r = s + (size_t)row*SEQ;
    float v[16];
    float m = -1e30f;
    #pragma unroll
    for(int i=0;i<16;i++){ v[i] = r[lane + i*32]; m = fmaxf(m, v[i]); }
    #pragma unroll
    for(int o=16;o;o>>=1) m = fmaxf(m, __shfl_xor_sync(~0u,m,o));
    float sum = 0.f;
    #pragma unroll
    for(int i=0;i<16;i++){ v[i] = __expf(v[i]-m); sum += v[i]; }
    #pragma unroll
    for(int o=16;o;o>>=1) sum += __shfl_xor_sync(~0u,sum,o);
    const float inv = 1.f/sum;
    #pragma unroll
    for(int i=0;i<16;i++) r[lane + i*32] = tf32r(v[i]*inv);
}

// ---------------- weight transpose [K,N] -> [N,K], rounded to tf32 --------------
__global__ void wtrans(const float* __restrict__ in, float* __restrict__ out, int K, int N){
    __shared__ float t[32][33];
    const int k0 = blockIdx.y*32, n0 = blockIdx.x*32;
    const int tx = threadIdx.x & 31, ty = threadIdx.x >> 5;
    #pragma unroll
    for(int i=0;i<4;i++)
        t[ty+8*i][tx] = in[(size_t)(k0+ty+8*i)*N + n0+tx];
    __syncthreads();
    #pragma unroll
    for(int i=0;i<4;i++)
        out[(size_t)(n0+ty+8*i)*K + k0+tx] = tf32r(t[tx][ty+8*i]);
}

__global__ void concat_bias(const float* a, const float* b, const float* c, float* o){
    int i = blockIdx.x*256 + threadIdx.x;
    if(i < DIMM){ o[i] = a[i]; o[i+DIMM] = b[i]; o[i+2*DIMM] = c[i]; }
}

// ---------------- host ----------------
static P2 mkp(const float* A, const float* B, float* C, const float* bias,
              const float* R, int lda, int ldb, int ldc, int ldr, int nk){
    P2 p{};
    p.A=A; p.B=B; p.C=C; p.bias=bias; p.R=R;
    p.lda=lda; p.ldb=ldb; p.ldc=ldc; p.ldr=ldr;
    p.sAb=p.sAh=p.sBb=p.sBh=p.sCb=p.sCh=p.sRb=p.sRh=0;
    p.H=1; p.scale=1.f; p.nk=nk;
    return p;
}

extern "C" void kernel_launch(void* const* d_in, const int* in_sizes, int n_in,
                              void* d_out, int out_size){
    const float* x    = (const float*)d_in[0];
    const float* ln_w = (const float*)d_in[1];
    const float* ln_b = (const float*)d_in[2];
    const float* wq   = (const float*)d_in[3];
    const float* bq   = (const float*)d_in[4];
    const float* wk   = (const float*)d_in[5];
    const float* bk   = (const float*)d_in[6];
    const float* wv   = (const float*)d_in[7];
    const float* bv   = (const float*)d_in[8];
    const float* w1   = (const float*)d_in[9];
    const float* b1   = (const float*)d_in[10];
    const float* w2   = (const float*)d_in[11];
    const float* b2   = (const float*)d_in[12];

    float *px, *px2, *pln, *pqkv, *pvt, *ps, *ph, *pwqkvT, *pw1T, *pw2T, *pbqkv;
    cudaGetSymbolAddress((void**)&px    , g_x   );
    cudaGetSymbolAddress((void**)&px2   , g_x2  );
    cudaGetSymbolAddress((void**)&pln   , g_ln  );
    cudaGetSymbolAddress((void**)&pqkv  , g_qkv );
    cudaGetSymbolAddress((void**)&pvt   , g_vt  );
    cudaGetSymbolAddress((void**)&ps    , g_s   );
    cudaGetSymbolAddress((void**)&ph    , g_h   );
    cudaGetSymbolAddress((void**)&pwqkvT, g_wqkvT);
    cudaGetSymbolAddress((void**)&pw1T  , g_w1T );
    cudaGetSymbolAddress((void**)&pw2T  , g_w2T );
    cudaGetSymbolAddress((void**)&pbqkv , g_bqkv);

    const int SM128 = 2*(128*32 + 128*32)*4;   // 65536
    const int SM64  = 2*(128*32 +  64*32)*4;   // 49152
    cudaFuncSetAttribute(gemm2<128,17>, cudaFuncAttributeMaxDynamicSharedMemorySize, SM128);
    cudaFuncSetAttribute(gemm2<128, 8>, cudaFuncAttributeMaxDynamicSharedMemorySize, SM128);
    cudaFuncSetAttribute(gemm2<128,19>, cudaFuncAttributeMaxDynamicSharedMemorySize, SM128);
    cudaFuncSetAttribute(gemm2<128, 5>, cudaFuncAttributeMaxDynamicSharedMemorySize, SM128);
    cudaFuncSetAttribute(gemm2< 64, 4>, cudaFuncAttributeMaxDynamicSharedMemorySize, SM64);

    // weight prep (amortized over 12 layers)
    wtrans<<<dim3(DIMM/32, DIMM/32), 256>>>(wq, pwqkvT,                       DIMM, DIMM);
    wtrans<<<dim3(DIMM/32, DIMM/32), 256>>>(wk, pwqkvT + (size_t)DIMM*DIMM,   DIMM, DIMM);
    wtrans<<<dim3(DIMM/32, DIMM/32), 256>>>(wv, pwqkvT + (size_t)2*DIMM*DIMM, DIMM, DIMM);
    wtrans<<<dim3(MLPD/32, DIMM/32), 256>>>(w1, pw1T, DIMM, MLPD);
    wtrans<<<dim3(DIMM/32, MLPD/32), 256>>>(w2, pw2T, MLPD, DIMM);
    concat_bias<<<3, 256>>>(bq, bk, bv, pbqkv);

    cudaMemcpyAsync(px, x, (size_t)MROWS*DIMM*sizeof(float), cudaMemcpyDeviceToDevice);

    for(int l=0; l<NDEPTH; l++){
        // --- attention block ---
        ln_kernel<<<MROWS,256>>>(px, ln_w, ln_b, pln);

        // fused QKV: [8192,2304] = ln * wqkvT^T ; bias + round to tf32
        { P2 p = mkp(pln, pwqkvT, pqkv, pbqkv, nullptr, DIMM, DIMM, QKVN, 0, DIMM/32);
          gemm2<128,17><<<dim3(QKVN/128, MROWS/128, 1), 256, SM128>>>(p); }

        vreform<<<dim3(SEQ/32, HDIM/32, NZ), 256>>>(pqkv, pvt);

        // scores: S = (Q K^T) * 1/8 ; B = K slice of qkv read as [N=keys, K=d]
        { P2 p = mkp(pqkv, pqkv + DIMM, ps, nullptr, nullptr, QKVN, QKVN, SEQ, 0, HDIM/32);
          p.H = NHEADS; p.scale = 0.125f;
          p.sAb = (long)SEQ*QKVN;       p.sAh = HDIM;
          p.sBb = (long)SEQ*QKVN;       p.sBh = HDIM;
          p.sCb = (long)NHEADS*SEQ*SEQ; p.sCh = (long)SEQ*SEQ;
          gemm2<128,8><<<dim3(SEQ/128, SEQ/128, NZ), 256, SM128>>>(p); }

        softmax_kernel<<<NZ*SEQ/8, 256>>>(ps);

        // AV: x2 = P V + x ; B = V^T per head [N=dout, K=keys]
        { P2 p = mkp(ps, pvt, px2, nullptr, px, SEQ, SEQ, DIMM, DIMM, SEQ/32);
          p.H = NHEADS;
          p.sAb = (long)NHEADS*SEQ*SEQ; p.sAh = (long)SEQ*SEQ;
          p.sBb = (long)NHEADS*HDIM*SEQ; p.sBh = (long)HDIM*SEQ;
          p.sCb = (long)SEQ*DIMM;       p.sCh = HDIM;
          p.sRb = (long)SEQ*DIMM;       p.sRh = HDIM;
          gemm2<64,4><<<dim3(1, SEQ/128, NZ), 256, SM64>>>(p); }

        // --- MLP block ---
        ln_kernel<<<MROWS,256>>>(px2, ln_w, ln_b, pln);

        { P2 p = mkp(pln, pw1T, ph, b1, nullptr, DIMM, DIMM, MLPD, 0, DIMM/32);
          gemm2<128,19><<<dim3(MLPD/128, MROWS/128, 1), 256, SM128>>>(p); }   // bias+gelu+round

        { P2 p = mkp(ph, pw2T, px, b2, px2, MLPD, MLPD, DIMM, DIMM, MLPD/32);
          gemm2<128,5><<<dim3(DIMM/128, MROWS/128, 1), 256, SM128>>>(p); }    // bias+resid
    }

    cudaMemcpyAsync(d_out, px, (size_t)MROWS*DIMM*sizeof(float), cudaMemcpyDeviceToDevice);
}

// round 4
// speedup vs baseline: 2.4595x; 2.3683x over previous
#include <cuda_runtime.h>
#include <cuda_fp16.h>
#include <math.h>
#include <stdint.h>

// Problem constants
#define DIMM   768
#define NHEADS 12
#define HDIM   64
#define MLPD   3072
#define NDEPTH 12
#define BATCH  16
#define SEQ    512
#define MROWS  (BATCH*SEQ)    // 8192
#define NZ     (BATCH*NHEADS) // 192
#define QKVN   (3*DIMM)       // 2304

// ---------------- scratch (static device, no allocation) ----------------
__device__ float  g_x  [(size_t)MROWS*DIMM];
__device__ float  g_x2 [(size_t)MROWS*DIMM];
__device__ float  g_bqkv[QKVN];
__device__ __half h_ln [(size_t)MROWS*DIMM];
__device__ __half h_qkv[(size_t)MROWS*QKVN];
__device__ __half h_vt [(size_t)NZ*HDIM*SEQ];      // per-head V^T: [z][d][n]
__device__ __half h_p  [(size_t)NZ*SEQ*SEQ];       // scores then probs (in place)
__device__ __half h_hid[(size_t)MROWS*MLPD];
__device__ __half h_wqkvT[(size_t)QKVN*DIMM];      // [2304,768] fp16, [N,K]
__device__ __half h_w1T [(size_t)MLPD*DIMM];
__device__ __half h_w2T [(size_t)DIMM*MLPD];

// ---------------- helpers ----------------
__device__ __forceinline__ float gelu_exact(float v){
    return 0.5f * v * (1.0f + erff(v * 0.70710678118654752440f));
}
__device__ __forceinline__ uint32_t smem_u32(const void* p){
    uint32_t a;
    asm("{ .reg .u64 t; cvta.to.shared.u64 t, %1; cvt.u32.u64 %0, t; }" : "=r"(a) : "l"(p));
    return a;
}
__device__ __forceinline__ void cpa16(uint32_t s, const void* g){
    asm volatile("cp.async.cg.shared.global [%0], [%1], 16;" :: "r"(s), "l"(g));
}
__device__ __forceinline__ void cpa_commit(){ asm volatile("cp.async.commit_group;" ::: "memory"); }
template<int N> __device__ __forceinline__ void cpa_wait(){
    asm volatile("cp.async.wait_group %0;" :: "n"(N) : "memory");
}
__device__ __forceinline__ void ldsm4(uint32_t* r, uint32_t addr){
    asm volatile("ldmatrix.sync.aligned.m8n8.x4.shared.b16 {%0,%1,%2,%3}, [%4];"
        : "=r"(r[0]), "=r"(r[1]), "=r"(r[2]), "=r"(r[3]) : "r"(addr));
}
__device__ __forceinline__ void mma_f16(float* d, const uint32_t* a, const uint32_t* b){
    asm volatile(
        "mma.sync.aligned.m16n8k16.row.col.f32.f16.f16.f32 "
        "{%0,%1,%2,%3}, {%4,%5,%6,%7}, {%8,%9}, {%0,%1,%2,%3};\n"
        : "+f"(d[0]), "+f"(d[1]), "+f"(d[2]), "+f"(d[3])
        : "r"(a[0]), "r"(a[1]), "r"(a[2]), "r"(a[3]), "r"(b[0]), "r"(b[1]));
}

// =========================================================================
// fp16 GEMM, fp32 accumulate:
//   C[M,N] = A[M,K](row, K contig, half) * B[N,K]^T (row, K contig, half)
//   BM=128, BN in {128,64}, BK=32, 4-stage cp.async, ldmatrix fragments.
//   8 warps as 2(m) x 4(n); warp tile 64 x BN/4; MT=4, NT=BN/32.
// Smem layout per stage: rows of 64B (32 halves), 16B unit u swizzled
//   u_s = u ^ ((row>>1)&3)   -> conflict-free LDSM and fine cp.async.
// EPI bits: 1=+bias, 2=gelu, 4=+residual(fp32), 8=*scale, 32=half out (else fp32)
// =========================================================================
struct PH {
    const __half* A; const __half* B; void* C;
    const float* bias; const float* R;
    int lda, ldb, ldc, ldr;
    long sAb, sAh, sBb, sBh, sCb, sCh, sRb, sRh;
    int H;
    float scale;
    int nk;         // K / 32
};

template<int BN, int EPI>
__global__ __launch_bounds__(256, 2) void gemmh(PH p){
    constexpr int BM = 128, S = 4;
    constexpr int ABYTES = BM*64;            // 8192
    constexpr int BBYTES = BN*64;
    constexpr int STAGE  = ABYTES + BBYTES;
    constexpr int WTN = BN/4, NT = WTN/8, MT = 4;
    constexpr int AIT = BM*4/256, BIT = BN*4/256;

    extern __shared__ char sm[];
    const uint32_t smb = smem_u32(sm);
    const int tid  = threadIdx.x;
    const int lane = tid & 31;
    const int warp = tid >> 5;
    const int wm   = warp >> 2;     // 0..1
    const int wn   = warp & 3;      // 0..3

    const int z  = blockIdx.z;
    const int zb = z / p.H, zh = z % p.H;

    const __half* Ag = p.A + (long)zb*p.sAb + (long)zh*p.sAh + (long)blockIdx.y*BM*p.lda;
    const __half* Bg = p.B + (long)zb*p.sBb + (long)zh*p.sBh + (long)blockIdx.x*BN*p.ldb;

    float acc[MT][NT][4];
    #pragma unroll
    for(int i=0;i<MT;i++)
        #pragma unroll
        for(int j=0;j<NT;j++){
            acc[i][j][0]=0.f; acc[i][j][1]=0.f; acc[i][j][2]=0.f; acc[i][j][3]=0.f;
        }

    auto load_stage = [&](int kt, int s){
        const uint32_t ab = smb + s*STAGE;
        #pragma unroll
        for(int t=0;t<AIT;t++){
            int i = tid + t*256, row = i>>2, u = i&3;
            uint32_t us = (uint32_t)u ^ (((uint32_t)row>>1)&3);
            cpa16(ab + row*64 + us*16, Ag + (long)row*p.lda + kt*32 + u*8);
        }
        const uint32_t bb = ab + ABYTES;
        #pragma unroll
        for(int t=0;t<BIT;t++){
            int i = tid + t*256, row = i>>2, u = i&3;
            uint32_t us = (uint32_t)u ^ (((uint32_t)row>>1)&3);
            cpa16(bb + row*64 + us*16, Bg + (long)row*p.ldb + kt*32 + u*8);
        }
    };

    const int nk = p.nk;
    #pragma unroll
    for(int s=0;s<S-1;s++){
        if(s < nk) load_stage(s, s);
        cpa_commit();
    }

    for(int kt = 0; kt < nk; kt++){
        cpa_wait<S-2>();
        __syncthreads();
        const uint32_t ab = smb + (kt & 3)*STAGE;
        const uint32_t bb = ab + ABYTES;

        #pragma unroll
        for(int ks=0; ks<2; ks++){
            uint32_t af[MT][4], bf[NT][2];
            #pragma unroll
            for(int mt=0; mt<MT; mt++){
                uint32_t row = (uint32_t)(wm*64 + mt*16 + ((lane>>3)&1)*8 + (lane&7));
                uint32_t u   = (uint32_t)(ks*2 + (lane>>4));
                ldsm4(af[mt], ab + row*64 + (u ^ ((row>>1)&3))*16);
            }
            #pragma unroll
            for(int j=0; j<NT/2; j++){
                uint32_t n = (uint32_t)(wn*WTN + j*16 + ((lane>>4)&1)*8 + (lane&7));
                uint32_t u = (uint32_t)(ks*2 + ((lane>>3)&1));
                uint32_t r4[4];
                ldsm4(r4, bb + n*64 + (u ^ ((n>>1)&3))*16);
                bf[2*j][0]=r4[0]; bf[2*j][1]=r4[1]; bf[2*j+1][0]=r4[2]; bf[2*j+1][1]=r4[3];
            }
            #pragma unroll
            for(int mt=0; mt<MT; mt++)
                #pragma unroll
                for(int nt=0; nt<NT; nt++)
                    mma_f16(acc[mt][nt], af[mt], bf[nt]);
        }

        const int nx = kt + S - 1;
        if(nx < nk) load_stage(nx, nx & 3);
        cpa_commit();
    }

    // ---------------- epilogue ----------------
    const long crow0 = (long)zb*p.sCb + (long)zh*p.sCh + (long)blockIdx.y*BM*p.ldc
                     + (long)blockIdx.x*BN;
    const float* Rg = nullptr;
    if(EPI & 4)
        Rg = p.R + (long)zb*p.sRb + (long)zh*p.sRh + (long)blockIdx.y*BM*p.ldr
                 + (long)blockIdx.x*BN;

    #pragma unroll
    for(int mt=0; mt<MT; mt++){
        #pragma unroll
        for(int nt=0; nt<NT; nt++){
            const int col = wn*WTN + nt*8 + 2*(lane&3);
            #pragma unroll
            for(int hh=0; hh<2; hh++){
                const int row = wm*64 + mt*16 + (lane>>2) + hh*8;
                float v0 = acc[mt][nt][hh*2], v1 = acc[mt][nt][hh*2+1];
                if(EPI & 8){ v0 *= p.scale; v1 *= p.scale; }
                if(EPI & 1){
                    const int gc = blockIdx.x*BN + col;
                    v0 += p.bias[gc]; v1 += p.bias[gc+1];
                }
                if(EPI & 2){ v0 = gelu_exact(v0); v1 = gelu_exact(v1); }
                if(EPI & 4){
                    float2 rv = *(const float2*)(Rg + (long)row*p.ldr + col);
                    v0 += rv.x; v1 += rv.y;
                }
                if(EPI & 32){
                    __half2* Ch = (__half2*)((__half*)p.C + crow0 + (long)row*p.ldc + col);
                    *Ch = __floats2half2_rn(v0, v1);
                }else{
                    float* Cf = (float*)p.C + crow0 + (long)row*p.ldc + col;
                    *(float2*)Cf = make_float2(v0, v1);
                }
            }
        }
    }
}

// ---------------- LayerNorm (row = 768), fp32 in -> fp16 out ----------------
__global__ void ln_kernel(const float* __restrict__ x, const float* __restrict__ w,
                          const float* __restrict__ b, __half* __restrict__ out){
    const int row = blockIdx.x;
    const int tid = threadIdx.x;
    const float* xr = x + (size_t)row*DIMM;
    float a0 = xr[tid], a1 = xr[tid+256], a2 = xr[tid+512];

    float s  = a0 + a1 + a2;
    float s2 = a0*a0 + a1*a1 + a2*a2;
    __shared__ float shs[8], shq[8];
    const int lane = tid & 31, wrp = tid >> 5;
    #pragma unroll
    for(int o=16;o;o>>=1){ s += __shfl_xor_sync(~0u,s,o); s2 += __shfl_xor_sync(~0u,s2,o); }
    if(lane==0){ shs[wrp]=s; shq[wrp]=s2; }
    __syncthreads();
    if(wrp==0){
        s  = (lane<8)? shs[lane] : 0.f;
        s2 = (lane<8)? shq[lane] : 0.f;
        #pragma unroll
        for(int o=4;o;o>>=1){ s += __shfl_xor_sync(~0u,s,o); s2 += __shfl_xor_sync(~0u,s2,o); }
        if(lane==0){ shs[0]=s; shq[0]=s2; }
    }
    __syncthreads();
    const float mu  = shs[0] * (1.f/DIMM);
    const float var = shq[0] * (1.f/DIMM) - mu*mu;
    const float inv = rsqrtf(var + 1e-5f);

    __half* orow = out + (size_t)row*DIMM;
    orow[tid    ] = __float2half_rn((a0 - mu)*inv*w[tid    ] + b[tid    ]);
    orow[tid+256] = __float2half_rn((a1 - mu)*inv*w[tid+256] + b[tid+256]);
    orow[tid+512] = __float2half_rn((a2 - mu)*inv*w[tid+512] + b[tid+512]);
}

// ---------------- V reformat: qkv V-cols -> per-head [z][d][n] (half) ----------
__global__ void vreform(const __half* __restrict__ qkv, __half* __restrict__ vt){
    __shared__ __half t[32][34];
    const int z = blockIdx.z, bb = z / NHEADS, hh = z % NHEADS;
    const int n0 = blockIdx.x*32, d0 = blockIdx.y*32;
    const int tx = threadIdx.x & 31, ty = threadIdx.x >> 5;
    #pragma unroll
    for(int k=0;k<4;k++){
        const int n = n0 + ty + 8*k;
        t[ty + 8*k][tx] = qkv[(size_t)(bb*SEQ + n)*QKVN + 2*DIMM + hh*HDIM + d0 + tx];
    }
    __syncthreads();
    #pragma unroll
    for(int k=0;k<4;k++){
        const int d = d0 + ty + 8*k;
        vt[((size_t)z*HDIM + d)*SEQ + n0 + tx] = t[tx][ty + 8*k];
    }
}

// ---------------- softmax over rows of 512 (warp per row), half in/out --------
__global__ void softmax_h(__half* __restrict__ s){
    const int row  = blockIdx.x*8 + (threadIdx.x >> 5);
    const int lane = threadIdx.x & 31;
    __half2* r = (__half2*)(s + (size_t)row*SEQ);
    float2 v[8];
    float m = -1e30f;
    #pragma unroll
    for(int i=0;i<8;i++){
        v[i] = __half22float2(r[lane + i*32]);
        m = fmaxf(m, fmaxf(v[i].x, v[i].y));
    }
    #pragma unroll
    for(int o=16;o;o>>=1) m = fmaxf(m, __shfl_xor_sync(~0u,m,o));
    float sum = 0.f;
    #pragma unroll
    for(int i=0;i<8;i++){
        v[i].x = __expf(v[i].x - m); v[i].y = __expf(v[i].y - m);
        sum += v[i].x + v[i].y;
    }
    #pragma unroll
    for(int o=16;o;o>>=1) sum += __shfl_xor_sync(~0u,sum,o);
    const float inv = 1.f/sum;
    #pragma unroll
    for(int i=0;i<8;i++)
        r[lane + i*32] = __floats2half2_rn(v[i].x*inv, v[i].y*inv);
}

// ---------------- weight transpose [K,N] fp32 -> [N,K] fp16 --------------------
__global__ void wtrans(const float* __restrict__ in, __half* __restrict__ out, int K, int N){
    __shared__ float t[32][33];
    const int k0 = blockIdx.y*32, n0 = blockIdx.x*32;
    const int tx = threadIdx.x & 31, ty = threadIdx.x >> 5;
    #pragma unroll
    for(int i=0;i<4;i++)
        t[ty+8*i][tx] = in[(size_t)(k0+ty+8*i)*N + n0+tx];
    __syncthreads();
    #pragma unroll
    for(int i=0;i<4;i++)
        out[(size_t)(n0+ty+8*i)*K + k0+tx] = __float2half_rn(t[tx][ty+8*i]);
}

__global__ void concat_bias(const float* a, const float* b, const float* c, float* o){
    int i = blockIdx.x*256 + threadIdx.x;
    if(i < DIMM){ o[i] = a[i]; o[i+DIMM] = b[i]; o[i+2*DIMM] = c[i]; }
}

// ---------------- host ----------------
static PH mkph(const __half* A, const __half* B, void* C, const float* bias,
               const float* R, int lda, int ldb, int ldc, int ldr, int nk){
    PH p{};
    p.A=A; p.B=B; p.C=C; p.bias=bias; p.R=R;
    p.lda=lda; p.ldb=ldb; p.ldc=ldc; p.ldr=ldr;
    p.sAb=p.sAh=p.sBb=p.sBh=p.sCb=p.sCh=p.sRb=p.sRh=0;
    p.H=1; p.scale=1.f; p.nk=nk;
    return p;
}

extern "C" void kernel_launch(void* const* d_in, const int* in_sizes, int n_in,
                              void* d_out, int out_size){
    const float* x    = (const float*)d_in[0];
    const float* ln_w = (const float*)d_in[1];
    const float* ln_b = (const float*)d_in[2];
    const float* wq   = (const float*)d_in[3];
    const float* bq   = (const float*)d_in[4];
    const float* wk   = (const float*)d_in[5];
    const float* bk   = (const float*)d_in[6];
    const float* wv   = (const float*)d_in[7];
    const float* bv   = (const float*)d_in[8];
    const float* w1   = (const float*)d_in[9];
    const float* b1   = (const float*)d_in[10];
    const float* w2   = (const float*)d_in[11];
    const float* b2   = (const float*)d_in[12];

    float *px, *px2, *pbqkv;
    __half *pln, *pqkv, *pvt, *pp, *phid, *pwqkvT, *pw1T, *pw2T;
    cudaGetSymbolAddress((void**)&px    , g_x   );
    cudaGetSymbolAddress((void**)&px2   , g_x2  );
    cudaGetSymbolAddress((void**)&pbqkv , g_bqkv);
    cudaGetSymbolAddress((void**)&pln   , h_ln  );
    cudaGetSymbolAddress((void**)&pqkv  , h_qkv );
    cudaGetSymbolAddress((void**)&pvt   , h_vt  );
    cudaGetSymbolAddress((void**)&pp    , h_p   );
    cudaGetSymbolAddress((void**)&phid  , h_hid );
    cudaGetSymbolAddress((void**)&pwqkvT, h_wqkvT);
    cudaGetSymbolAddress((void**)&pw1T  , h_w1T );
    cudaGetSymbolAddress((void**)&pw2T  , h_w2T );

    const int SM128 = 4*(128*64 + 128*64);   // 65536
    const int SM64  = 4*(128*64 +  64*64);   // 49152
    cudaFuncSetAttribute(gemmh<128,33>, cudaFuncAttributeMaxDynamicSharedMemorySize, SM128);
    cudaFuncSetAttribute(gemmh<128,40>, cudaFuncAttributeMaxDynamicSharedMemorySize, SM128);
    cudaFuncSetAttribute(gemmh<128,35>, cudaFuncAttributeMaxDynamicSharedMemorySize, SM128);
    cudaFuncSetAttribute(gemmh<128, 5>, cudaFuncAttributeMaxDynamicSharedMemorySize, SM128);
    cudaFuncSetAttribute(gemmh< 64, 4>, cudaFuncAttributeMaxDynamicSharedMemorySize, SM64);

    // weight prep (amortized over 12 layers)
    wtrans<<<dim3(DIMM/32, DIMM/32), 256>>>(wq, pwqkvT,                       DIMM, DIMM);
    wtrans<<<dim3(DIMM/32, DIMM/32), 256>>>(wk, pwqkvT + (size_t)DIMM*DIMM,   DIMM, DIMM);
    wtrans<<<dim3(DIMM/32, DIMM/32), 256>>>(wv, pwqkvT + (size_t)2*DIMM*DIMM, DIMM, DIMM);
    wtrans<<<dim3(MLPD/32, DIMM/32), 256>>>(w1, pw1T, DIMM, MLPD);
    wtrans<<<dim3(DIMM/32, MLPD/32), 256>>>(w2, pw2T, MLPD, DIMM);
    concat_bias<<<3, 256>>>(bq, bk, bv, pbqkv);

    cudaMemcpyAsync(px, x, (size_t)MROWS*DIMM*sizeof(float), cudaMemcpyDeviceToDevice);

    for(int l=0; l<NDEPTH; l++){
        // --- attention block ---
        ln_kernel<<<MROWS,256>>>(px, ln_w, ln_b, pln);

        // fused QKV: [8192,2304] ; bias, half out
        { PH p = mkph(pln, pwqkvT, pqkv, pbqkv, nullptr, DIMM, DIMM, QKVN, 0, DIMM/32);
          gemmh<128,33><<<dim3(QKVN/128, MROWS/128, 1), 256, SM128>>>(p); }

        vreform<<<dim3(SEQ/32, HDIM/32, NZ), 256>>>(pqkv, pvt);

        // scores: S = (Q K^T) * 1/8 ; half out
        { PH p = mkph(pqkv, pqkv + DIMM, pp, nullptr, nullptr, QKVN, QKVN, SEQ, 0, HDIM/32);
          p.H = NHEADS; p.scale = 0.125f;
          p.sAb = (long)SEQ*QKVN;       p.sAh = HDIM;
          p.sBb = (long)SEQ*QKVN;       p.sBh = HDIM;
          p.sCb = (long)NHEADS*SEQ*SEQ; p.sCh = (long)SEQ*SEQ;
          gemmh<128,40><<<dim3(SEQ/128, SEQ/128, NZ), 256, SM128>>>(p); }

        softmax_h<<<NZ*SEQ/8, 256>>>(pp);

        // AV: x2 = P V + x (fp32 out, residual fused)
        { PH p = mkph(pp, pvt, px2, nullptr, px, SEQ, SEQ, DIMM, DIMM, SEQ/32);
          p.H = NHEADS;
          p.sAb = (long)NHEADS*SEQ*SEQ;  p.sAh = (long)SEQ*SEQ;
          p.sBb = (long)NHEADS*HDIM*SEQ; p.sBh = (long)HDIM*SEQ;
          p.sCb = (long)SEQ*DIMM;        p.sCh = HDIM;
          p.sRb = (long)SEQ*DIMM;        p.sRh = HDIM;
          gemmh<64,4><<<dim3(1, SEQ/128, NZ), 256, SM64>>>(p); }

        // --- MLP block ---
        ln_kernel<<<MROWS,256>>>(px2, ln_w, ln_b, pln);

        { PH p = mkph(pln, pw1T, phid, b1, nullptr, DIMM, DIMM, MLPD, 0, DIMM/32);
          gemmh<128,35><<<dim3(MLPD/128, MROWS/128, 1), 256, SM128>>>(p); }   // bias+gelu+half

        { PH p = mkph(phid, pw2T, px, b2, px2, MLPD, MLPD, DIMM, DIMM, MLPD/32);
          gemmh<128,5><<<dim3(DIMM/128, MROWS/128, 1), 256, SM128>>>(p); }    // bias+resid fp32
    }

    cudaMemcpyAsync(d_out, px, (size_t)MROWS*DIMM*sizeof(float), cudaMemcpyDeviceToDevice);
}

// round 6
// speedup vs baseline: 2.8766x; 1.1696x over previous
#include <cuda_runtime.h>
#include <cuda_fp16.h>
#include <math.h>
#include <stdint.h>

// Problem constants
#define DIMM   768
#define NHEADS 12
#define HDIM   64
#define MLPD   3072
#define NDEPTH 12
#define BATCH  16
#define SEQ    512
#define MROWS  (BATCH*SEQ)    // 8192
#define NZ     (BATCH*NHEADS) // 192
#define QKVN   (3*DIMM)       // 2304

// ---------------- scratch (static device, no allocation) ----------------
__device__ float  g_x  [(size_t)MROWS*DIMM];
__device__ float  g_x2 [(size_t)MROWS*DIMM];
__device__ float  g_bqkv[QKVN];
__device__ __half h_ln [(size_t)MROWS*DIMM];
__device__ __half h_qkv[(size_t)MROWS*QKVN];
__device__ __half h_hid[(size_t)MROWS*MLPD];
__device__ __half h_wqkvT[(size_t)QKVN*DIMM];      // [2304,768] fp16, [N,K]
__device__ __half h_w1T [(size_t)MLPD*DIMM];
__device__ __half h_w2T [(size_t)DIMM*MLPD];

// ---------------- helpers ----------------
__device__ __forceinline__ float gelu_exact(float v){
    return 0.5f * v * (1.0f + erff(v * 0.70710678118654752440f));
}
__device__ __forceinline__ uint32_t smem_u32(const void* p){
    uint32_t a;
    asm("{ .reg .u64 t; cvta.to.shared.u64 t, %1; cvt.u32.u64 %0, t; }" : "=r"(a) : "l"(p));
    return a;
}
__device__ __forceinline__ void cpa16(uint32_t s, const void* g){
    asm volatile("cp.async.cg.shared.global [%0], [%1], 16;" :: "r"(s), "l"(g));
}
__device__ __forceinline__ void cpa_commit(){ asm volatile("cp.async.commit_group;" ::: "memory"); }
template<int N> __device__ __forceinline__ void cpa_wait(){
    asm volatile("cp.async.wait_group %0;" :: "n"(N) : "memory");
}
__device__ __forceinline__ void ldsm4(uint32_t* r, uint32_t addr){
    asm volatile("ldmatrix.sync.aligned.m8n8.x4.shared.b16 {%0,%1,%2,%3}, [%4];"
        : "=r"(r[0]), "=r"(r[1]), "=r"(r[2]), "=r"(r[3]) : "r"(addr));
}
__device__ __forceinline__ void ldsm4t(uint32_t* r, uint32_t addr){
    asm volatile("ldmatrix.sync.aligned.m8n8.x4.trans.shared.b16 {%0,%1,%2,%3}, [%4];"
        : "=r"(r[0]), "=r"(r[1]), "=r"(r[2]), "=r"(r[3]) : "r"(addr));
}
__device__ __forceinline__ void mma_f16(float* d, const uint32_t* a, const uint32_t* b){
    asm volatile(
        "mma.sync.aligned.m16n8k16.row.col.f32.f16.f16.f32 "
        "{%0,%1,%2,%3}, {%4,%5,%6,%7}, {%8,%9}, {%0,%1,%2,%3};\n"
        : "+f"(d[0]), "+f"(d[1]), "+f"(d[2]), "+f"(d[3])
        : "r"(a[0]), "r"(a[1]), "r"(a[2]), "r"(a[3]), "r"(b[0]), "r"(b[1]));
}
__device__ __forceinline__ uint32_t packh2(float x, float y){
    __half2 h = __floats2half2_rn(x, y);
    return *(uint32_t*)&h;
}

// =========================================================================
// fp16 GEMM, fp32 accumulate:
//   C[M,N] = A[M,K](row, K contig, half) * B[N,K]^T (row, K contig, half)
// EPI bits: 1=+bias, 2=gelu, 4=+residual(fp32), 8=*scale, 32=half out
// =========================================================================
struct PH {
    const __half* A; const __half* B; void* C;
    const float* bias; const float* R;
    int lda, ldb, ldc, ldr;
    long sAb, sAh, sBb, sBh, sCb, sCh, sRb, sRh;
    int H;
    float scale;
    int nk;         // K / 32
};

template<int BN, int EPI>
__global__ __launch_bounds__(256, 2) void gemmh(PH p){
    constexpr int BM = 128, S = 4;
    constexpr int ABYTES = BM*64;
    constexpr int BBYTES = BN*64;
    constexpr int STAGE  = ABYTES + BBYTES;
    constexpr int WTN = BN/4, NT = WTN/8, MT = 4;
    constexpr int AIT = BM*4/256, BIT = BN*4/256;

    extern __shared__ char sm[];
    const uint32_t smb = smem_u32(sm);
    const int tid  = threadIdx.x;
    const int lane = tid & 31;
    const int warp = tid >> 5;
    const int wm   = warp >> 2;
    const int wn   = warp & 3;

    const int z  = blockIdx.z;
    const int zb = z / p.H, zh = z % p.H;

    const __half* Ag = p.A + (long)zb*p.sAb + (long)zh*p.sAh + (long)blockIdx.y*BM*p.lda;
    const __half* Bg = p.B + (long)zb*p.sBb + (long)zh*p.sBh + (long)blockIdx.x*BN*p.ldb;

    float acc[MT][NT][4];
    #pragma unroll
    for(int i=0;i<MT;i++)
        #pragma unroll
        for(int j=0;j<NT;j++){
            acc[i][j][0]=0.f; acc[i][j][1]=0.f; acc[i][j][2]=0.f; acc[i][j][3]=0.f;
        }

    auto load_stage = [&](int kt, int s){
        const uint32_t ab = smb + s*STAGE;
        #pragma unroll
        for(int t=0;t<AIT;t++){
            int i = tid + t*256, row = i>>2, u = i&3;
            uint32_t us = (uint32_t)u ^ (((uint32_t)row>>1)&3);
            cpa16(ab + row*64 + us*16, Ag + (long)row*p.lda + kt*32 + u*8);
        }
        const uint32_t bb = ab + ABYTES;
        #pragma unroll
        for(int t=0;t<BIT;t++){
            int i = tid + t*256, row = i>>2, u = i&3;
            uint32_t us = (uint32_t)u ^ (((uint32_t)row>>1)&3);
            cpa16(bb + row*64 + us*16, Bg + (long)row*p.ldb + kt*32 + u*8);
        }
    };

    const int nk = p.nk;
    #pragma unroll
    for(int s=0;s<S-1;s++){
        if(s < nk) load_stage(s, s);
        cpa_commit();
    }

    for(int kt = 0; kt < nk; kt++){
        cpa_wait<S-2>();
        __syncthreads();
        const uint32_t ab = smb + (kt & 3)*STAGE;
        const uint32_t bb = ab + ABYTES;

        #pragma unroll
        for(int ks=0; ks<2; ks++){
            uint32_t af[MT][4], bf[NT][2];
            #pragma unroll
            for(int mt=0; mt<MT; mt++){
                uint32_t row = (uint32_t)(wm*64 + mt*16 + ((lane>>3)&1)*8 + (lane&7));
                uint32_t u   = (uint32_t)(ks*2 + (lane>>4));
                ldsm4(af[mt], ab + row*64 + (u ^ ((row>>1)&3))*16);
            }
            #pragma unroll
            for(int j=0; j<NT/2; j++){
                uint32_t n = (uint32_t)(wn*WTN + j*16 + ((lane>>4)&1)*8 + (lane&7));
                uint32_t u = (uint32_t)(ks*2 + ((lane>>3)&1));
                uint32_t r4[4];
                ldsm4(r4, bb + n*64 + (u ^ ((n>>1)&3))*16);
                bf[2*j][0]=r4[0]; bf[2*j][1]=r4[1]; bf[2*j+1][0]=r4[2]; bf[2*j+1][1]=r4[3];
            }
            #pragma unroll
            for(int mt=0; mt<MT; mt++)
                #pragma unroll
                for(int nt=0; nt<NT; nt++)
                    mma_f16(acc[mt][nt], af[mt], bf[nt]);
        }

        const int nx = kt + S - 1;
        if(nx < nk) load_stage(nx, nx & 3);
        cpa_commit();
    }

    const long crow0 = (long)zb*p.sCb + (long)zh*p.sCh + (long)blockIdx.y*BM*p.ldc
                     + (long)blockIdx.x*BN;
    const float* Rg = nullptr;
    if(EPI & 4)
        Rg = p.R + (long)zb*p.sRb + (long)zh*p.sRh + (long)blockIdx.y*BM*p.ldr
                 + (long)blockIdx.x*BN;

    #pragma unroll
    for(int mt=0; mt<MT; mt++){
        #pragma unroll
        for(int nt=0; nt<NT; nt++){
            const int col = wn*WTN + nt*8 + 2*(lane&3);
            #pragma unroll
            for(int hh=0; hh<2; hh++){
                const int row = wm*64 + mt*16 + (lane>>2) + hh*8;
                float v0 = acc[mt][nt][hh*2], v1 = acc[mt][nt][hh*2+1];
                if(EPI & 8){ v0 *= p.scale; v1 *= p.scale; }
                if(EPI & 1){
                    const int gc = blockIdx.x*BN + col;
                    v0 += p.bias[gc]; v1 += p.bias[gc+1];
                }
                if(EPI & 2){ v0 = gelu_exact(v0); v1 = gelu_exact(v1); }
                if(EPI & 4){
                    float2 rv = *(const float2*)(Rg + (long)row*p.ldr + col);
                    v0 += rv.x; v1 += rv.y;
                }
                if(EPI & 32){
                    __half2* Ch = (__half2*)((__half*)p.C + crow0 + (long)row*p.ldc + col);
                    *Ch = __floats2half2_rn(v0, v1);
                }else{
                    float* Cf = (float*)p.C + crow0 + (long)row*p.ldc + col;
                    *(float2*)Cf = make_float2(v0, v1);
                }
            }
        }
    }
}

// =========================================================================
// Fused flash attention: out = softmax(Q K^T / 8) V + xres
// Grid: (SEQ/128, NZ). 256 threads = 8 warps; warp w owns query rows
// [w*16, w*16+16). Keys streamed in 4 blocks of 128 (2-stage cp.async).
// K, V read directly from the fused QKV buffer. fp32 online softmax.
// Smem tiles: rows of 64 halves = 128B, unit swizzle u ^= (row&7).
// =========================================================================
__global__ __launch_bounds__(256, 1) void flash(
    const __half* __restrict__ qkv, const float* __restrict__ xres,
    float* __restrict__ out)
{
    extern __shared__ char sm[];
    const uint32_t smb = smem_u32(sm);
    const uint32_t qs  = smb;                       // 16KB Q
    const int tid = threadIdx.x, lane = tid & 31, warp = tid >> 5;
    const int z = blockIdx.y, zb = z / NHEADS, zh = z % NHEADS;
    const long grow0 = (long)zb*SEQ + (long)blockIdx.x*128;

    const __half* Qg = qkv + grow0*QKVN + zh*HDIM;
    const __half* Kg = qkv + (long)zb*SEQ*QKVN + DIMM   + zh*HDIM;
    const __half* Vg = qkv + (long)zb*SEQ*QKVN + 2*DIMM + zh*HDIM;

    auto ldtile = [&](uint32_t dst, const __half* src){
        #pragma unroll
        for(int t=0;t<4;t++){
            int i = tid + t*256, row = i>>3;
            uint32_t u = (uint32_t)(i&7);
            cpa16(dst + (uint32_t)row*128 + (u ^ ((uint32_t)row&7))*16,
                  src + (long)row*QKVN + u*8);
        }
    };

    // Q, then KV blocks 0 and 1  (groups: {Q}, {K0V0}, {K1V1})
    ldtile(qs, Qg);                                                       cpa_commit();
    ldtile(smb+16384, Kg);             ldtile(smb+32768, Vg);             cpa_commit();
    ldtile(smb+49152, Kg + 128l*QKVN); ldtile(smb+65536, Vg + 128l*QKVN); cpa_commit();

    cpa_wait<2>();
    __syncthreads();

    // Q fragments (rows warp*16 .. +16, K-dim = 64)
    uint32_t qf[4][4];
    #pragma unroll
    for(int ks=0; ks<4; ks++){
        uint32_t row = (uint32_t)(warp*16 + ((lane>>3)&1)*8 + (lane&7));
        uint32_t u   = (uint32_t)(2*ks + (lane>>4));
        ldsm4(qf[ks], qs + row*128 + (u ^ (row&7))*16);
    }

    float m0 = -1e30f, m1 = -1e30f, l0 = 0.f, l1 = 0.f;
    float o[8][4];
    #pragma unroll
    for(int nt=0;nt<8;nt++){ o[nt][0]=0.f; o[nt][1]=0.f; o[nt][2]=0.f; o[nt][3]=0.f; }

    for(int kb=0; kb<4; kb++){
        if(kb < 2) cpa_wait<1>(); else cpa_wait<0>();
        __syncthreads();
        const uint32_t kbuf = smb + 16384 + (uint32_t)(kb&1)*32768;
        const uint32_t vbuf = kbuf + 16384;

        // ---- S = Q K^T ----
        float s[16][4];
        #pragma unroll
        for(int nt=0;nt<16;nt++){ s[nt][0]=0.f; s[nt][1]=0.f; s[nt][2]=0.f; s[nt][3]=0.f; }
        #pragma unroll
        for(int ks=0; ks<4; ks++){
            uint32_t bf[16][2];
            #pragma unroll
            for(int j=0;j<8;j++){
                uint32_t n = (uint32_t)(j*16 + ((lane>>4)&1)*8 + (lane&7));
                uint32_t u = (uint32_t)(2*ks + ((lane>>3)&1));
                uint32_t r4[4];
                ldsm4(r4, kbuf + n*128 + (u ^ (n&7))*16);
                bf[2*j][0]=r4[0]; bf[2*j][1]=r4[1]; bf[2*j+1][0]=r4[2]; bf[2*j+1][1]=r4[3];
            }
            #pragma unroll
            for(int nt=0;nt<16;nt++) mma_f16(s[nt], qf[ks], bf[nt]);
        }

        // ---- online softmax (rows r = warp*16 + lane>>2 and r+8) ----
        float cm0 = -1e30f, cm1 = -1e30f;
        #pragma unroll
        for(int nt=0;nt<16;nt++){
            s[nt][0]*=0.125f; s[nt][1]*=0.125f; s[nt][2]*=0.125f; s[nt][3]*=0.125f;
            cm0 = fmaxf(cm0, fmaxf(s[nt][0], s[nt][1]));
            cm1 = fmaxf(cm1, fmaxf(s[nt][2], s[nt][3]));
        }
        cm0 = fmaxf(cm0, __shfl_xor_sync(~0u,cm0,1));
        cm0 = fmaxf(cm0, __shfl_xor_sync(~0u,cm0,2));
        cm1 = fmaxf(cm1, __shfl_xor_sync(~0u,cm1,1));
        cm1 = fmaxf(cm1, __shfl_xor_sync(~0u,cm1,2));
        const float mn0 = fmaxf(m0, cm0), mn1 = fmaxf(m1, cm1);
        const float sf0 = __expf(m0 - mn0), sf1 = __expf(m1 - mn1);
        float sum0 = 0.f, sum1 = 0.f;
        #pragma unroll
        for(int nt=0;nt<16;nt++){
            s[nt][0] = __expf(s[nt][0]-mn0); s[nt][1] = __expf(s[nt][1]-mn0);
            s[nt][2] = __expf(s[nt][2]-mn1); s[nt][3] = __expf(s[nt][3]-mn1);
            sum0 += s[nt][0] + s[nt][1];
            sum1 += s[nt][2] + s[nt][3];
        }
        sum0 += __shfl_xor_sync(~0u,sum0,1); sum0 += __shfl_xor_sync(~0u,sum0,2);
        sum1 += __shfl_xor_sync(~0u,sum1,1); sum1 += __shfl_xor_sync(~0u,sum1,2);
        l0 = l0*sf0 + sum0; l1 = l1*sf1 + sum1;
        m0 = mn0; m1 = mn1;
        #pragma unroll
        for(int nt=0;nt<8;nt++){
            o[nt][0]*=sf0; o[nt][1]*=sf0; o[nt][2]*=sf1; o[nt][3]*=sf1;
        }

        // ---- O += P V  (P from registers; V via ldmatrix.trans) ----
        #pragma unroll
        for(int kk=0; kk<8; kk++){
            uint32_t pa[4];
            pa[0] = packh2(s[2*kk  ][0], s[2*kk  ][1]);
            pa[1] = packh2(s[2*kk  ][2], s[2*kk  ][3]);
            pa[2] = packh2(s[2*kk+1][0], s[2*kk+1][1]);
            pa[3] = packh2(s[2*kk+1][2], s[2*kk+1][3]);
            uint32_t bf[8][2];
            const int g = lane>>3, i = lane&7;
            #pragma unroll
            for(int dp=0; dp<4; dp++){
                uint32_t key = (uint32_t)(kk*16 + (g&1)*8 + i);
                uint32_t dg  = (uint32_t)(dp*2 + (g>>1));
                uint32_t r4[4];
                ldsm4t(r4, vbuf + key*128 + (dg ^ (key&7))*16);
                bf[2*dp][0]=r4[0]; bf[2*dp][1]=r4[1]; bf[2*dp+1][0]=r4[2]; bf[2*dp+1][1]=r4[3];
            }
            #pragma unroll
            for(int nt=0;nt<8;nt++) mma_f16(o[nt], pa, bf[nt]);
        }

        __syncthreads();
        if(kb + 2 < 4){
            ldtile(smb+16384+(uint32_t)(kb&1)*32768, Kg + (long)(kb+2)*128*QKVN);
            ldtile(smb+32768+(uint32_t)(kb&1)*32768, Vg + (long)(kb+2)*128*QKVN);
            cpa_commit();
        }
    }

    // ---- epilogue: O/l + residual, fp32 out ----
    const float inv0 = 1.f/l0, inv1 = 1.f/l1;
    const long gr0 = grow0 + warp*16 + (lane>>2);
    const long gr1 = gr0 + 8;
    const int  col = zh*HDIM + 2*(lane&3);
    #pragma unroll
    for(int nt=0; nt<8; nt++){
        const int c = col + nt*8;
        float2 r0 = *(const float2*)&xres[gr0*DIMM + c];
        float2 r1 = *(const float2*)&xres[gr1*DIMM + c];
        *(float2*)&out[gr0*DIMM + c] = make_float2(o[nt][0]*inv0 + r0.x, o[nt][1]*inv0 + r0.y);
        *(float2*)&out[gr1*DIMM + c] = make_float2(o[nt][2]*inv1 + r1.x, o[nt][3]*inv1 + r1.y);
    }
}

// ---------------- LayerNorm (row = 768), fp32 in -> fp16 out ----------------
__global__ void ln_kernel(const float* __restrict__ x, const float* __restrict__ w,
                          const float* __restrict__ b, __half* __restrict__ out){
    const int row = blockIdx.x;
    const int tid = threadIdx.x;
    const float* xr = x + (size_t)row*DIMM;
    float a0 = xr[tid], a1 = xr[tid+256], a2 = xr[tid+512];

    float s  = a0 + a1 + a2;
    float s2 = a0*a0 + a1*a1 + a2*a2;
    __shared__ float shs[8], shq[8];
    const int lane = tid & 31, wrp = tid >> 5;
    #pragma unroll
    for(int o=16;o;o>>=1){ s += __shfl_xor_sync(~0u,s,o); s2 += __shfl_xor_sync(~0u,s2,o); }
    if(lane==0){ shs[wrp]=s; shq[wrp]=s2; }
    __syncthreads();
    if(wrp==0){
        s  = (lane<8)? shs[lane] : 0.f;
        s2 = (lane<8)? shq[lane] : 0.f;
        #pragma unroll
        for(int o=4;o;o>>=1){ s += __shfl_xor_sync(~0u,s,o); s2 += __shfl_xor_sync(~0u,s2,o); }
        if(lane==0){ shs[0]=s; shq[0]=s2; }
    }
    __syncthreads();
    const float mu  = shs[0] * (1.f/DIMM);
    const float var = shq[0] * (1.f/DIMM) - mu*mu;
    const float inv = rsqrtf(var + 1e-5f);

    __half* orow = out + (size_t)row*DIMM;
    orow[tid    ] = __float2half_rn((a0 - mu)*inv*w[tid    ] + b[tid    ]);
    orow[tid+256] = __float2half_rn((a1 - mu)*inv*w[tid+256] + b[tid+256]);
    orow[tid+512] = __float2half_rn((a2 - mu)*inv*w[tid+512] + b[tid+512]);
}

// ---------------- weight transpose [K,N] fp32 -> [N,K] fp16 --------------------
__global__ void wtrans(const float* __restrict__ in, __half* __restrict__ out, int K, int N){
    __shared__ float t[32][33];
    const int k0 = blockIdx.y*32, n0 = blockIdx.x*32;
    const int tx = threadIdx.x & 31, ty = threadIdx.x >> 5;
    #pragma unroll
    for(int i=0;i<4;i++)
        t[ty+8*i][tx] = in[(size_t)(k0+ty+8*i)*N + n0+tx];
    __syncthreads();
    #pragma unroll
    for(int i=0;i<4;i++)
        out[(size_t)(n0+ty+8*i)*K + k0+tx] = __float2half_rn(t[tx][ty+8*i]);
}

__global__ void concat_bias(const float* a, const float* b, const float* c, float* o){
    int i = blockIdx.x*256 + threadIdx.x;
    if(i < DIMM){ o[i] = a[i]; o[i+DIMM] = b[i]; o[i+2*DIMM] = c[i]; }
}

// ---------------- host ----------------
static PH mkph(const __half* A, const __half* B, void* C, const float* bias,
               const float* R, int lda, int ldb, int ldc, int ldr, int nk){
    PH p{};
    p.A=A; p.B=B; p.C=C; p.bias=bias; p.R=R;
    p.lda=lda; p.ldb=ldb; p.ldc=ldc; p.ldr=ldr;
    p.sAb=p.sAh=p.sBb=p.sBh=p.sCb=p.sCh=p.sRb=p.sRh=0;
    p.H=1; p.scale=1.f; p.nk=nk;
    return p;
}

extern "C" void kernel_launch(void* const* d_in, const int* in_sizes, int n_in,
                              void* d_out, int out_size){
    const float* x    = (const float*)d_in[0];
    const float* ln_w = (const float*)d_in[1];
    const float* ln_b = (const float*)d_in[2];
    const float* wq   = (const float*)d_in[3];
    const float* bq   = (const float*)d_in[4];
    const float* wk   = (const float*)d_in[5];
    const float* bk   = (const float*)d_in[6];
    const float* wv   = (const float*)d_in[7];
    const float* bv   = (const float*)d_in[8];
    const float* w1   = (const float*)d_in[9];
    const float* b1   = (const float*)d_in[10];
    const float* w2   = (const float*)d_in[11];
    const float* b2   = (const float*)d_in[12];

    float *px, *px2, *pbqkv;
    __half *pln, *pqkv, *phid, *pwqkvT, *pw1T, *pw2T;
    cudaGetSymbolAddress((void**)&px    , g_x   );
    cudaGetSymbolAddress((void**)&px2   , g_x2  );
    cudaGetSymbolAddress((void**)&pbqkv , g_bqkv);
    cudaGetSymbolAddress((void**)&pln   , h_ln  );
    cudaGetSymbolAddress((void**)&pqkv  , h_qkv );
    cudaGetSymbolAddress((void**)&phid  , h_hid );
    cudaGetSymbolAddress((void**)&pwqkvT, h_wqkvT);
    cudaGetSymbolAddress((void**)&pw1T  , h_w1T );
    cudaGetSymbolAddress((void**)&pw2T  , h_w2T );

    const int SM128 = 4*(128*64 + 128*64);   // 65536
    const int SMFL  = 16384 + 2*32768;       // 81920: Q + 2 KV stages
    cudaFuncSetAttribute(gemmh<128,33>, cudaFuncAttributeMaxDynamicSharedMemorySize, SM128);
    cudaFuncSetAttribute(gemmh<128,35>, cudaFuncAttributeMaxDynamicSharedMemorySize, SM128);
    cudaFuncSetAttribute(gemmh<128, 5>, cudaFuncAttributeMaxDynamicSharedMemorySize, SM128);
    cudaFuncSetAttribute(flash,         cudaFuncAttributeMaxDynamicSharedMemorySize, SMFL);

    // weight prep (amortized over 12 layers)
    wtrans<<<dim3(DIMM/32, DIMM/32), 256>>>(wq, pwqkvT,                       DIMM, DIMM);
    wtrans<<<dim3(DIMM/32, DIMM/32), 256>>>(wk, pwqkvT + (size_t)DIMM*DIMM,   DIMM, DIMM);
    wtrans<<<dim3(DIMM/32, DIMM/32), 256>>>(wv, pwqkvT + (size_t)2*DIMM*DIMM, DIMM, DIMM);
    wtrans<<<dim3(MLPD/32, DIMM/32), 256>>>(w1, pw1T, DIMM, MLPD);
    wtrans<<<dim3(DIMM/32, MLPD/32), 256>>>(w2, pw2T, MLPD, DIMM);
    concat_bias<<<3, 256>>>(bq, bk, bv, pbqkv);

    cudaMemcpyAsync(px, x, (size_t)MROWS*DIMM*sizeof(float), cudaMemcpyDeviceToDevice);

    for(int l=0; l<NDEPTH; l++){
        // --- attention block ---
        ln_kernel<<<MROWS,256>>>(px, ln_w, ln_b, pln);

        // fused QKV: [8192,2304] ; bias, half out
        { PH p = mkph(pln, pwqkvT, pqkv, pbqkv, nullptr, DIMM, DIMM, QKVN, 0, DIMM/32);
          gemmh<128,33><<<dim3(QKVN/128, MROWS/128, 1), 256, SM128>>>(p); }

        // fused attention: x2 = softmax(QK^T/8)V + x
        flash<<<dim3(SEQ/128, NZ), 256, SMFL>>>(pqkv, px, px2);

        // --- MLP block ---
        ln_kernel<<<MROWS,256>>>(px2, ln_w, ln_b, pln);

        { PH p = mkph(pln, pw1T, phid, b1, nullptr, DIMM, DIMM, MLPD, 0, DIMM/32);
          gemmh<128,35><<<dim3(MLPD/128, MROWS/128, 1), 256, SM128>>>(p); }   // bias+gelu+half

        { PH p = mkph(phid, pw2T, px, b2, px2, MLPD, MLPD, DIMM, DIMM, MLPD/32);
          gemmh<128,5><<<dim3(DIMM/128, MROWS/128, 1), 256, SM128>>>(p); }    // bias+resid fp32
    }

    cudaMemcpyAsync(d_out, px, (size_t)MROWS*DIMM*sizeof(float), cudaMemcpyDeviceToDevice);
}